// round 7
// baseline (speedup 1.0000x reference)
#include <cuda_runtime.h>
#include <cstdint>

// GlobalMixer: y[b,h,o,g] = sum_i W[h,o,i] * x[b,h,i,g]
//   x: (B=512, H=512, SEQ=256) fp32, SEQ elem (i,g) at i*16+g
//   W: (H=512, 16, 16) fp32
//
// R7: address-density test. All prior variants pin at ~6.4 TB/s effective
// regardless of occ / L1 / demand smoothness. Last untested lever: DRAM row
// locality. CTA now owns 32 CONSECUTIVE h at 2 b values -> contiguous
// 2 x 32KB read + write windows; the concurrent CTA wave covers a dense
// ~40MB span instead of spraying the full 268MB. W staged per-CTA (32 rows,
// L2-hit) with stride-260 padding so 8 distinct h-rows/warp are LDS
// conflict-free. Compute shape identical to R3 (proven fastest).

#define HIDDEN 512
#define BATCH  512
#define H_PER_CTA 32
#define B_PER_CTA 2
#define WPAD 260   // floats per h row in smem: 1040B, 8 rows span 8 distinct 16B lanes

__device__ __forceinline__ unsigned long long fma2(unsigned long long a,
                                                   unsigned long long b,
                                                   unsigned long long c) {
    unsigned long long d;
    asm("fma.rn.f32x2 %0, %1, %2, %3;" : "=l"(d) : "l"(a), "l"(b), "l"(c));
    return d;
}

__device__ __forceinline__ unsigned long long splat2(float w) {
    unsigned long long d;
    asm("mov.b64 %0, {%1, %1};" : "=l"(d) : "f"(w));
    return d;
}

__global__ __launch_bounds__(256, 2)
void global_mixer_kernel(const float* __restrict__ x,
                         const float* __restrict__ W,
                         float* __restrict__ y) {
    __shared__ float ws[H_PER_CTA * WPAD];    // 33,280 B

    const int h0 = blockIdx.x * H_PER_CTA;    // 0,32,..,480
    const int t  = threadIdx.x;               // 0..255

    // Stage W[h0 .. h0+31] (8 KFloats, all L2-hits; coalesced 1KB/step)
    for (int idx = t; idx < H_PER_CTA * 256; idx += 256) {
        const int hl = idx >> 8, j = idx & 255;
        ws[hl * WPAD + j] = W[(h0 + hl) * 256 + j];
    }
    __syncthreads();

    const int b_sel   = t >> 7;        // 0..1
    const int h_local = (t >> 2) & 31; // 0..31  (8 consecutive h per warp)
    const int gq      = t & 3;         // g-quad -> g = 4*gq .. 4*gq+3

    const int b = blockIdx.y * B_PER_CTA + b_sel;
    const size_t base = ((size_t)b * HIDDEN + h0 + h_local) * 256 + gq * 4;
    const ulonglong2* __restrict__ xp =
        reinterpret_cast<const ulonglong2*>(x + base);
    ulonglong2* __restrict__ yp =
        reinterpret_cast<ulonglong2*>(y + base);
    const float* __restrict__ wrow_base = &ws[h_local * WPAD];

    // Front-batch 16 x LDG.128 (evict-first), stride 16 floats
    ulonglong2 xv[16];
#pragma unroll
    for (int i = 0; i < 16; i++) xv[i] = __ldcs(xp + (size_t)i * 4);

#pragma unroll
    for (int o = 0; o < 16; o++) {
        unsigned long long alo = 0ull, ahi = 0ull;
        const float4* __restrict__ wrow =
            reinterpret_cast<const float4*>(wrow_base + o * 16);
#pragma unroll
        for (int i4 = 0; i4 < 4; i4++) {
            float4 w = wrow[i4];              // LDS.128: conflict-free (WPAD)
            unsigned long long w0 = splat2(w.x);
            unsigned long long w1 = splat2(w.y);
            unsigned long long w2 = splat2(w.z);
            unsigned long long w3 = splat2(w.w);
            alo = fma2(xv[4 * i4 + 0].x, w0, alo);
            ahi = fma2(xv[4 * i4 + 0].y, w0, ahi);
            alo = fma2(xv[4 * i4 + 1].x, w1, alo);
            ahi = fma2(xv[4 * i4 + 1].y, w1, ahi);
            alo = fma2(xv[4 * i4 + 2].x, w2, alo);
            ahi = fma2(xv[4 * i4 + 2].y, w2, ahi);
            alo = fma2(xv[4 * i4 + 3].x, w3, alo);
            ahi = fma2(xv[4 * i4 + 3].y, w3, ahi);
        }
        ulonglong2 out; out.x = alo; out.y = ahi;
        __stcs(yp + (size_t)o * 4, out);      // STG.128 streaming
    }
}

extern "C" void kernel_launch(void* const* d_in, const int* in_sizes, int n_in,
                              void* d_out, int out_size) {
    const float* x = (const float*)d_in[0];   // 512*512*256 fp32
    const float* W = (const float*)d_in[1];   // 512*16*16 fp32
    float* y = (float*)d_out;

    // blockIdx.x = h-chunk (fastest) -> consecutive CTAs are address-adjacent
    dim3 grid(HIDDEN / H_PER_CTA, BATCH / B_PER_CTA);   // (16, 256)
    global_mixer_kernel<<<grid, 256>>>(x, W, y);
}

// round 8
// speedup vs baseline: 1.3260x; 1.3260x over previous
#include <cuda_runtime.h>
#include <cstdint>

// GlobalMixer: y[b,h,o,g] = sum_i W[h,o,i] * x[b,h,i,g]
//   x: (B=512, H=512, SEQ=256) fp32, SEQ elem (i,g) at i*16+g
//   W: (H=512, 16, 16) fp32
//
// R8: R3 (best: 84.5us) + x-load hoist. The 16 DRAM loads were issued only
// after the W-load -> STS -> __syncthreads chain, exposing ~600cyc of
// startup latency per CTA slot. They don't depend on the barrier: issue
// them FIRST so the DRAM fetch overlaps W staging. Everything else is the
// proven R3 shape (g-quad, unsplatted W in smem, packed f32x2 FMA,
// streaming .cs loads/stores).
//
// Hypothesis ledger (R4 occ / R6 smoothness / R7 locality all neutral-or-
// worse): kernel is at the ~6.4 TB/s mixed R/W HBM wall; this harvests the
// last verified startup inefficiency.

#define HIDDEN 512
#define BATCH  512
#define B_PER_BLOCK 64

__device__ __forceinline__ unsigned long long fma2(unsigned long long a,
                                                   unsigned long long b,
                                                   unsigned long long c) {
    unsigned long long d;
    asm("fma.rn.f32x2 %0, %1, %2, %3;" : "=l"(d) : "l"(a), "l"(b), "l"(c));
    return d;
}

__device__ __forceinline__ unsigned long long splat2(float w) {
    unsigned long long d;
    asm("mov.b64 %0, {%1, %1};" : "=l"(d) : "f"(w));
    return d;
}

__global__ __launch_bounds__(256, 2)
void global_mixer_kernel(const float* __restrict__ x,
                         const float* __restrict__ W,
                         float* __restrict__ y) {
    __shared__ float ws[256];               // W[h] plain fp32, 1 KB

    const int h  = blockIdx.x;              // 0..511
    const int b0 = blockIdx.y * B_PER_BLOCK;
    const int t  = threadIdx.x;             // 0..255

    const int b_local = t >> 2;   // 0..63
    const int gq      = t & 3;    // g-quad -> g = 4*gq .. 4*gq+3

    const size_t base = ((size_t)(b0 + b_local) * HIDDEN + h) * 256 + gq * 4;
    const ulonglong2* __restrict__ xp =
        reinterpret_cast<const ulonglong2*>(x + base);
    ulonglong2* __restrict__ yp =
        reinterpret_cast<ulonglong2*>(y + base);

    // Issue the 16 DRAM loads FIRST (independent of the barrier below):
    // their ~600cyc latency overlaps the W L2-load + STS + BAR chain.
    ulonglong2 xv[16];
#pragma unroll
    for (int i = 0; i < 16; i++) xv[i] = __ldcs(xp + (size_t)i * 4);

    ws[t] = W[h * 256 + t];                 // W is L2-resident (512 KB)
    __syncthreads();

#pragma unroll
    for (int o = 0; o < 16; o++) {
        unsigned long long alo = 0ull, ahi = 0ull;
        const float4* __restrict__ wrow =
            reinterpret_cast<const float4*>(&ws[o * 16]);
#pragma unroll
        for (int i4 = 0; i4 < 4; i4++) {
            float4 w = wrow[i4];            // LDS.128: 4 distinct W values
            unsigned long long w0 = splat2(w.x);
            unsigned long long w1 = splat2(w.y);
            unsigned long long w2 = splat2(w.z);
            unsigned long long w3 = splat2(w.w);
            alo = fma2(xv[4 * i4 + 0].x, w0, alo);
            ahi = fma2(xv[4 * i4 + 0].y, w0, ahi);
            alo = fma2(xv[4 * i4 + 1].x, w1, alo);
            ahi = fma2(xv[4 * i4 + 1].y, w1, ahi);
            alo = fma2(xv[4 * i4 + 2].x, w2, alo);
            ahi = fma2(xv[4 * i4 + 2].y, w2, ahi);
            alo = fma2(xv[4 * i4 + 3].x, w3, alo);
            ahi = fma2(xv[4 * i4 + 3].y, w3, ahi);
        }
        ulonglong2 out; out.x = alo; out.y = ahi;
        __stcs(yp + (size_t)o * 4, out);    // STG.128 streaming, coalesced
    }
}

extern "C" void kernel_launch(void* const* d_in, const int* in_sizes, int n_in,
                              void* d_out, int out_size) {
    const float* x = (const float*)d_in[0];   // 512*512*256 fp32
    const float* W = (const float*)d_in[1];   // 512*16*16 fp32
    float* y = (float*)d_out;

    dim3 grid(HIDDEN, BATCH / B_PER_BLOCK);   // (512, 8)
    global_mixer_kernel<<<grid, 256>>>(x, W, y);
}

// round 9
// speedup vs baseline: 1.3316x; 1.0043x over previous
#include <cuda_runtime.h>
#include <cstdint>

// GlobalMixer: y[b,h,o,g] = sum_i W[h,o,i] * x[b,h,i,g]
//   x: (B=512, H=512, SEQ=256) fp32, SEQ elem (i,g) at i*16+g
//   W: (H=512, 16, 16) fp32
//
// R9: R8 (82.4us, hoisted x-loads) split into 128-thread CTAs, 4 CTAs/SM.
// R8 proved exposed CTA-startup latency is the active margin: 4 independent
// CTA phases per SM (vs 2) interleave store-tails with load-heads twice as
// finely, and the barrier now couples only 4 warps. Per-thread code
// unchanged (g-quad, unsplatted smem W, packed f32x2 FMA, .cs streams).

#define HIDDEN 512
#define BATCH  512
#define B_PER_BLOCK 32
#define THREADS 128

__device__ __forceinline__ unsigned long long fma2(unsigned long long a,
                                                   unsigned long long b,
                                                   unsigned long long c) {
    unsigned long long d;
    asm("fma.rn.f32x2 %0, %1, %2, %3;" : "=l"(d) : "l"(a), "l"(b), "l"(c));
    return d;
}

__device__ __forceinline__ unsigned long long splat2(float w) {
    unsigned long long d;
    asm("mov.b64 %0, {%1, %1};" : "=l"(d) : "f"(w));
    return d;
}

__global__ __launch_bounds__(THREADS, 4)
void global_mixer_kernel(const float* __restrict__ x,
                         const float* __restrict__ W,
                         float* __restrict__ y) {
    __shared__ float ws[256];               // W[h] plain fp32, 1 KB

    const int h  = blockIdx.x;              // 0..511
    const int b0 = blockIdx.y * B_PER_BLOCK;
    const int t  = threadIdx.x;             // 0..127

    const int b_local = t >> 2;   // 0..31
    const int gq      = t & 3;    // g-quad -> g = 4*gq .. 4*gq+3

    const size_t base = ((size_t)(b0 + b_local) * HIDDEN + h) * 256 + gq * 4;
    const ulonglong2* __restrict__ xp =
        reinterpret_cast<const ulonglong2*>(x + base);
    ulonglong2* __restrict__ yp =
        reinterpret_cast<ulonglong2*>(y + base);

    // DRAM loads FIRST: overlap their latency with the W L2-load + STS + BAR
    ulonglong2 xv[16];
#pragma unroll
    for (int i = 0; i < 16; i++) xv[i] = __ldcs(xp + (size_t)i * 4);

    // W stage: 128 threads x 2 elements (L2-resident)
    ws[t]       = W[h * 256 + t];
    ws[t + 128] = W[h * 256 + t + 128];
    __syncthreads();

#pragma unroll
    for (int o = 0; o < 16; o++) {
        unsigned long long alo = 0ull, ahi = 0ull;
        const float4* __restrict__ wrow =
            reinterpret_cast<const float4*>(&ws[o * 16]);
#pragma unroll
        for (int i4 = 0; i4 < 4; i4++) {
            float4 w = wrow[i4];            // LDS.128: 4 distinct W values
            unsigned long long w0 = splat2(w.x);
            unsigned long long w1 = splat2(w.y);
            unsigned long long w2 = splat2(w.z);
            unsigned long long w3 = splat2(w.w);
            alo = fma2(xv[4 * i4 + 0].x, w0, alo);
            ahi = fma2(xv[4 * i4 + 0].y, w0, ahi);
            alo = fma2(xv[4 * i4 + 1].x, w1, alo);
            ahi = fma2(xv[4 * i4 + 1].y, w1, ahi);
            alo = fma2(xv[4 * i4 + 2].x, w2, alo);
            ahi = fma2(xv[4 * i4 + 2].y, w2, ahi);
            alo = fma2(xv[4 * i4 + 3].x, w3, alo);
            ahi = fma2(xv[4 * i4 + 3].y, w3, ahi);
        }
        ulonglong2 out; out.x = alo; out.y = ahi;
        __stcs(yp + (size_t)o * 4, out);    // STG.128 streaming, coalesced
    }
}

extern "C" void kernel_launch(void* const* d_in, const int* in_sizes, int n_in,
                              void* d_out, int out_size) {
    const float* x = (const float*)d_in[0];   // 512*512*256 fp32
    const float* W = (const float*)d_in[1];   // 512*16*16 fp32
    float* y = (float*)d_out;

    dim3 grid(HIDDEN, BATCH / B_PER_BLOCK);   // (512, 16)
    global_mixer_kernel<<<grid, THREADS>>>(x, W, y);
}